// round 2
// baseline (speedup 1.0000x reference)
#include <cuda_runtime.h>
#include <cuda_bf16.h>
#include <cstdint>

// CRF mean NLL:  mean_b( log_partition_b - path_score_b )
// emissions: (16384, 512, 5) f32   transitions: (5,5) f32
// start/end: (5,) f32              tags: (16384,512) i32   mask: all-ones (ignored)
//
// Strategy: 1 thread per sequence. Forward pass kept as unnormalized
// probabilities w[5] + log offset c, with E=exp(T) precomputed, so each step is
// 5 exps + 25 FMA instead of full logsumexp. Renormalize every CHUNK=8 steps.
// Emissions staged through double-buffered SMEM via cp.async (coalesced),
// tags register-prefetched. Scalar reduction via atomicAdd into d_out.

#define TPB     128
#define CHUNK   8
#define L_SEQ   512
#define NCHUNK  (L_SEQ / CHUNK)          // 64
#define NBLOCK  128                      // 16384 / 128
#define ROWF4   10                       // CHUNK*5 floats = 10 float4 per seq per chunk
#define BUF_F4  (TPB * ROWF4)            // 1280 float4 per buffer
#define BUF_BYTES (BUF_F4 * 16)          // 20480

__device__ __forceinline__ void cp_async16(uint32_t saddr, const void* gptr) {
    asm volatile("cp.async.cg.shared.global [%0], [%1], 16;\n" :: "r"(saddr), "l"(gptr));
}
__device__ __forceinline__ void cp_commit() {
    asm volatile("cp.async.commit_group;\n");
}
__device__ __forceinline__ void cp_wait0() {
    asm volatile("cp.async.wait_group 0;\n");
}

__global__ void zero_out_kernel(float* out) {
    out[0] = 0.0f;
}

__global__ __launch_bounds__(TPB, 1)
void crf_nll_kernel(const float* __restrict__ em,
                    const float* __restrict__ trans,
                    const float* __restrict__ startT,
                    const float* __restrict__ endT,
                    const int*   __restrict__ tags,
                    float* __restrict__ out)
{
    __shared__ float4 s_em[2][BUF_F4];       // 40 KB double buffer
    __shared__ float  s_T[25];
    __shared__ float  s_start[5];
    __shared__ float  s_end[5];
    __shared__ float  s_red[TPB / 32];

    const int tid = threadIdx.x;
    const int b   = blockIdx.x * TPB + tid;          // sequence id

    if (tid < 25) s_T[tid] = trans[tid];
    if (tid < 5)  { s_start[tid] = startT[tid]; s_end[tid] = endT[tid]; }

    // exp(T) in registers (broadcast loads, computed once)
    float E[25];
#pragma unroll
    for (int i = 0; i < 25; ++i) E[i] = __expf(__ldg(&trans[i]));

    // ---- precompute per-thread copy addressing (coalesced mapping) ----
    const float4* gem = reinterpret_cast<const float4*>(em);
    const long blockSeq0 = (long)blockIdx.x * TPB;
    const float4* srcBase[ROWF4];
    uint32_t      dstOff[ROWF4];
#pragma unroll
    for (int k = 0; k < ROWF4; ++k) {
        int idx = tid + k * TPB;          // 0..1279 within block chunk
        int sq  = idx / ROWF4;            // local sequence
        int v   = idx - sq * ROWF4;       // float4 within row
        srcBase[k] = gem + (blockSeq0 + sq) * (L_SEQ * 5 / 4) + v;
        dstOff[k]  = (uint32_t)__cvta_generic_to_shared(&s_em[0][sq * ROWF4 + v]);
    }

    // tags pointer for this sequence (int4 = 4 timesteps)
    const int4* gtg = reinterpret_cast<const int4*>(tags) + (long)b * (L_SEQ / 4);

    // ---- prologue: issue chunk 0 copy, prefetch chunk 0 tags ----
#pragma unroll
    for (int k = 0; k < ROWF4; ++k)
        cp_async16(dstOff[k], srcBase[k]);
    cp_commit();
    int4 tga = __ldg(&gtg[0]);
    int4 tgb = __ldg(&gtg[1]);

    float w0 = 0.f, w1 = 0.f, w2 = 0.f, w3 = 0.f, w4 = 0.f;
    float c = 0.0f, num = 0.0f;
    int prev = 0;

#pragma unroll 1
    for (int chunk = 0; chunk < NCHUNK; ++chunk) {
        const int buf = chunk & 1;

        cp_wait0();                 // chunk's data landed (this thread's copies)
        __syncthreads();            // all threads' copies visible; prev compute done

        // prefetch next chunk (copy overlaps with compute below)
        int4 ntga = tga, ntgb = tgb;
        if (chunk + 1 < NCHUNK) {
            const int nbuf = buf ^ 1;
#pragma unroll
            for (int k = 0; k < ROWF4; ++k)
                cp_async16(dstOff[k] + nbuf * BUF_BYTES,
                           srcBase[k] + (chunk + 1) * ROWF4);
            cp_commit();
            ntga = __ldg(&gtg[2 * (chunk + 1)]);
            ntgb = __ldg(&gtg[2 * (chunk + 1) + 1]);
        }

        // pull this thread's contiguous row into registers (LDS.128)
        float emv[CHUNK * 5];
        const float4* rowp = &s_em[buf][tid * ROWF4];
#pragma unroll
        for (int v = 0; v < ROWF4; ++v) {
            float4 q = rowp[v];
            emv[4*v+0] = q.x; emv[4*v+1] = q.y; emv[4*v+2] = q.z; emv[4*v+3] = q.w;
        }
        const int tgs[8] = {tga.x, tga.y, tga.z, tga.w, tgb.x, tgb.y, tgb.z, tgb.w};
        const bool first_chunk = (chunk == 0);

#pragma unroll
        for (int tt = 0; tt < CHUNK; ++tt) {
            const float m0 = emv[tt*5+0], m1 = emv[tt*5+1], m2 = emv[tt*5+2],
                        m3 = emv[tt*5+3], m4 = emv[tt*5+4];
            const int tg = tgs[tt];

            // emission at gold tag (register selects, no dynamic indexing)
            float es = m0;
            es = (tg == 1) ? m1 : es;
            es = (tg == 2) ? m2 : es;
            es = (tg == 3) ? m3 : es;
            es = (tg == 4) ? m4 : es;

            if (tt == 0 && first_chunk) {
                // t == 0: init forward state and path score
                w0 = __expf(s_start[0] + m0);
                w1 = __expf(s_start[1] + m1);
                w2 = __expf(s_start[2] + m2);
                w3 = __expf(s_start[3] + m3);
                w4 = __expf(s_start[4] + m4);
                num = s_start[tg] + es;
            } else {
                const float e0 = __expf(m0), e1 = __expf(m1), e2 = __expf(m2),
                            e3 = __expf(m3), e4 = __expf(m4);
                const float a0 = fmaf(w4, E[20], fmaf(w3, E[15], fmaf(w2, E[10], fmaf(w1, E[5],  w0 * E[0]))));
                const float a1 = fmaf(w4, E[21], fmaf(w3, E[16], fmaf(w2, E[11], fmaf(w1, E[6],  w0 * E[1]))));
                const float a2 = fmaf(w4, E[22], fmaf(w3, E[17], fmaf(w2, E[12], fmaf(w1, E[7],  w0 * E[2]))));
                const float a3 = fmaf(w4, E[23], fmaf(w3, E[18], fmaf(w2, E[13], fmaf(w1, E[8],  w0 * E[3]))));
                const float a4 = fmaf(w4, E[24], fmaf(w3, E[19], fmaf(w2, E[14], fmaf(w1, E[9],  w0 * E[4]))));
                w0 = e0 * a0; w1 = e1 * a1; w2 = e2 * a2; w3 = e3 * a3; w4 = e4 * a4;
                num += s_T[prev * 5 + tg] + es;
            }
            prev = tg;
        }

        // renormalize every CHUNK steps (bounded growth: 8*(max|em|+1.71) << 88)
        const float mx = fmaxf(fmaxf(w0, w1), fmaxf(fmaxf(w2, w3), w4));
        c += __logf(mx);
        const float inv = __fdividef(1.0f, mx);
        w0 *= inv; w1 *= inv; w2 *= inv; w3 *= inv; w4 *= inv;

        tga = ntga; tgb = ntgb;
    }

    // ---- epilogue: log partition + end transitions ----
    const float ee0 = __expf(s_end[0]), ee1 = __expf(s_end[1]), ee2 = __expf(s_end[2]),
                ee3 = __expf(s_end[3]), ee4 = __expf(s_end[4]);
    const float sden = fmaf(w4, ee4, fmaf(w3, ee3, fmaf(w2, ee2, fmaf(w1, ee1, w0 * ee0))));
    const float den  = c + __logf(sden);
    num += s_end[prev];

    float val = den - num;

    // ---- block reduction + atomic accumulate of the mean ----
#pragma unroll
    for (int off = 16; off > 0; off >>= 1)
        val += __shfl_down_sync(0xffffffffu, val, off);
    const int lane = tid & 31, wid = tid >> 5;
    if (lane == 0) s_red[wid] = val;
    __syncthreads();
    if (tid == 0) {
        float s = s_red[0] + s_red[1] + s_red[2] + s_red[3];
        atomicAdd(out, s * (1.0f / 16384.0f));
    }
}

extern "C" void kernel_launch(void* const* d_in, const int* in_sizes, int n_in,
                              void* d_out, int out_size)
{
    const float* em     = (const float*)d_in[0];
    const float* trans  = (const float*)d_in[1];
    const float* startT = (const float*)d_in[2];
    const float* endT   = (const float*)d_in[3];
    const int*   tags   = (const int*)  d_in[4];
    // d_in[5] = mask: all ones in this problem -> ignored
    float* out = (float*)d_out;

    zero_out_kernel<<<1, 1>>>(out);
    crf_nll_kernel<<<NBLOCK, TPB>>>(em, trans, startT, endT, tags, out);
}

// round 3
// speedup vs baseline: 1.4037x; 1.4037x over previous
#include <cuda_runtime.h>
#include <cuda_bf16.h>
#include <cstdint>

// CRF mean NLL, warp-autonomous version.
// emissions (16384,512,5) f32; transitions (5,5); start/end (5,); tags (16384,512) i32; mask all-ones.
//
// 1 thread = 1 sequence; 1 warp = 1 CTA = 32 sequences; 512 CTAs cover all SMs.
// Forward state kept as unnormalized probs w[5] + log offset, E=exp(T) precomputed:
// per step = 5 exp + 25 FMA + 5 MUL. Renormalize every 8 steps.
// Emissions+tags staged through a 4-deep cp.async pipeline (prefetch distance 3),
// per-warp groups, __syncwarp only (no block barriers).

#define TPB         32
#define CHUNK       8
#define L_SEQ       512
#define NCHUNK      (L_SEQ / CHUNK)      // 64
#define GRID        512
#define SEQ_PER_CTA 32
#define DATA_F4     10                   // CHUNK*5 floats = 10 float4 per seq per chunk
#define ROW_F4      11                   // padded -> conflict-free LDS.128
#define TAG_F4      2                    // CHUNK tags = 2 int4
#define TROW_F4     3                    // padded
#define NBUF        4
#define EM_ROW_GF4  (L_SEQ * 5 / 4)      // 640 float4 per sequence
#define TG_ROW_GI4  (L_SEQ / 4)          // 128 int4 per sequence

__device__ float        g_partial[GRID];
__device__ unsigned int g_ticket = 0;

__device__ __forceinline__ void cp_async16(uint32_t saddr, const void* gptr) {
    asm volatile("cp.async.cg.shared.global [%0], [%1], 16;\n" :: "r"(saddr), "l"(gptr));
}
__device__ __forceinline__ void cp_commit() {
    asm volatile("cp.async.commit_group;\n");
}
__device__ __forceinline__ void cp_wait2() {
    asm volatile("cp.async.wait_group 2;\n");
}

__global__ __launch_bounds__(TPB)
void crf_nll_kernel(const float* __restrict__ em,
                    const float* __restrict__ trans,
                    const float* __restrict__ startT,
                    const float* __restrict__ endT,
                    const int*   __restrict__ tags,
                    float* __restrict__ out)
{
    __shared__ float4 s_em[NBUF][SEQ_PER_CTA * ROW_F4];   // 22528 B
    __shared__ int4   s_tg[NBUF][SEQ_PER_CTA * TROW_F4];  //  6144 B
    __shared__ float  s_T[25], s_start[5], s_end[5];

    const int  lane = threadIdx.x;
    const long seq0 = (long)blockIdx.x * SEQ_PER_CTA;

    if (lane < 25) s_T[lane] = trans[lane];
    if (lane < 5)  { s_start[lane] = startT[lane]; s_end[lane] = endT[lane]; }

    // exp(T) in registers (broadcast loads)
    float E[25];
#pragma unroll
    for (int i = 0; i < 25; ++i) E[i] = __expf(__ldg(&trans[i]));

    // ---- per-lane copy addressing (coalesced-ish: contiguous runs per sequence) ----
    const float4* gem = reinterpret_cast<const float4*>(em);
    const int4*   gtg = reinterpret_cast<const int4*>(tags);

    const float4* esrc[DATA_F4];  uint32_t edst[DATA_F4];
#pragma unroll
    for (int k = 0; k < DATA_F4; ++k) {
        int idx = lane + 32 * k;               // 0..319
        int sq  = idx / DATA_F4;               // local sequence 0..31
        int v   = idx - sq * DATA_F4;          // float4 within row
        esrc[k] = gem + (seq0 + sq) * EM_ROW_GF4 + v;
        edst[k] = (uint32_t)__cvta_generic_to_shared(&s_em[0][sq * ROW_F4 + v]);
    }
    const int4* tsrc[TAG_F4];  uint32_t tdst[TAG_F4];
#pragma unroll
    for (int k = 0; k < TAG_F4; ++k) {
        int idx = lane + 32 * k;               // 0..63
        int sq  = idx >> 1;
        int v   = idx & 1;
        tsrc[k] = gtg + (seq0 + sq) * TG_ROW_GI4 + v;
        tdst[k] = (uint32_t)__cvta_generic_to_shared(&s_tg[0][sq * TROW_F4 + v]);
    }

    const uint32_t EMBUF = (uint32_t)sizeof(s_em[0]);
    const uint32_t TGBUF = (uint32_t)sizeof(s_tg[0]);

    // ---- prologue: issue chunks 0..2 (3 groups in flight) ----
#pragma unroll
    for (int c = 0; c < 3; ++c) {
#pragma unroll
        for (int k = 0; k < DATA_F4; ++k)
            cp_async16(edst[k] + (uint32_t)c * EMBUF, esrc[k] + c * DATA_F4);
#pragma unroll
        for (int k = 0; k < TAG_F4; ++k)
            cp_async16(tdst[k] + (uint32_t)c * TGBUF, tsrc[k] + c * TAG_F4);
        cp_commit();
    }

    float w0 = 0.f, w1 = 0.f, w2 = 0.f, w3 = 0.f, w4 = 0.f;
    float clog = 0.f, num = 0.f;
    int prev = 0;

#pragma unroll 1
    for (int c = 0; c < NCHUNK; ++c) {
        const int buf = c & 3;

        cp_wait2();        // own group for chunk c retired (<=2 pending)
        __syncwarp();      // all lanes' copies for chunk c visible

        // prefetch chunk c+3 (commit ALWAYS -> uniform group count for wait_group 2)
        {
            const int pc = c + 3;
            if (pc < NCHUNK) {
                const uint32_t pb = (uint32_t)(pc & 3);
#pragma unroll
                for (int k = 0; k < DATA_F4; ++k)
                    cp_async16(edst[k] + pb * EMBUF, esrc[k] + pc * DATA_F4);
#pragma unroll
                for (int k = 0; k < TAG_F4; ++k)
                    cp_async16(tdst[k] + pb * TGBUF, tsrc[k] + pc * TAG_F4);
            }
            cp_commit();
        }

        // unpack this lane's contiguous row (conflict-free LDS.128, stride 11 f4)
        float m[CHUNK * 5];
        {
            const float4* rowp = &s_em[buf][lane * ROW_F4];
#pragma unroll
            for (int v = 0; v < DATA_F4; ++v) {
                float4 q = rowp[v];
                m[4*v+0] = q.x; m[4*v+1] = q.y; m[4*v+2] = q.z; m[4*v+3] = q.w;
            }
        }
        int tg8[8];
        {
            const int4* trow = &s_tg[buf][lane * TROW_F4];
            int4 ta = trow[0], tb = trow[1];
            tg8[0]=ta.x; tg8[1]=ta.y; tg8[2]=ta.z; tg8[3]=ta.w;
            tg8[4]=tb.x; tg8[5]=tb.y; tg8[6]=tb.z; tg8[7]=tb.w;
        }

#pragma unroll
        for (int t = 0; t < CHUNK; ++t) {
            const float m0 = m[t*5+0], m1 = m[t*5+1], m2 = m[t*5+2],
                        m3 = m[t*5+3], m4 = m[t*5+4];
            const int tg = tg8[t];

            float es = m0;
            es = (tg == 1) ? m1 : es;
            es = (tg == 2) ? m2 : es;
            es = (tg == 3) ? m3 : es;
            es = (tg == 4) ? m4 : es;

            if (t == 0 && c == 0) {
                w0 = __expf(s_start[0] + m0);
                w1 = __expf(s_start[1] + m1);
                w2 = __expf(s_start[2] + m2);
                w3 = __expf(s_start[3] + m3);
                w4 = __expf(s_start[4] + m4);
                num = s_start[tg] + es;
            } else {
                const float e0 = __expf(m0), e1 = __expf(m1), e2 = __expf(m2),
                            e3 = __expf(m3), e4 = __expf(m4);
                const float a0 = fmaf(w4, E[20], fmaf(w3, E[15], fmaf(w2, E[10], fmaf(w1, E[5],  w0 * E[0]))));
                const float a1 = fmaf(w4, E[21], fmaf(w3, E[16], fmaf(w2, E[11], fmaf(w1, E[6],  w0 * E[1]))));
                const float a2 = fmaf(w4, E[22], fmaf(w3, E[17], fmaf(w2, E[12], fmaf(w1, E[7],  w0 * E[2]))));
                const float a3 = fmaf(w4, E[23], fmaf(w3, E[18], fmaf(w2, E[13], fmaf(w1, E[8],  w0 * E[3]))));
                const float a4 = fmaf(w4, E[24], fmaf(w3, E[19], fmaf(w2, E[14], fmaf(w1, E[9],  w0 * E[4]))));
                w0 = e0 * a0; w1 = e1 * a1; w2 = e2 * a2; w3 = e3 * a3; w4 = e4 * a4;
                num += s_T[prev * 5 + tg] + es;
            }
            prev = tg;
        }

        // renormalize every 8 steps (growth bound 8*(max|em|+1.8) < 88 -> no overflow)
        const float mx  = fmaxf(fmaxf(w0, w1), fmaxf(fmaxf(w2, w3), w4));
        clog += __logf(mx);
        const float inv = __fdividef(1.0f, mx);
        w0 *= inv; w1 *= inv; w2 *= inv; w3 *= inv; w4 *= inv;
    }

    // ---- epilogue: log partition + gold end transition ----
    const float sden = fmaf(w4, __expf(s_end[4]),
                       fmaf(w3, __expf(s_end[3]),
                       fmaf(w2, __expf(s_end[2]),
                       fmaf(w1, __expf(s_end[1]), w0 * __expf(s_end[0])))));
    const float den = clog + __logf(sden);
    num += s_end[prev];

    float val = den - num;

    // ---- warp reduce + last-CTA global reduction (no pre-zero kernel needed) ----
#pragma unroll
    for (int off = 16; off > 0; off >>= 1)
        val += __shfl_down_sync(0xffffffffu, val, off);

    if (lane == 0) {
        g_partial[blockIdx.x] = val;
        __threadfence();
    }
    unsigned tk = 0;
    if (lane == 0) tk = atomicInc(&g_ticket, GRID - 1);   // wraps back to 0 -> replay-safe
    tk = __shfl_sync(0xffffffffu, tk, 0);

    if (tk == GRID - 1) {       // last CTA to arrive
        __threadfence();
        float s = 0.0f;
#pragma unroll
        for (int i = lane; i < GRID; i += 32) {
            float p;
            asm volatile("ld.global.cv.f32 %0, [%1];" : "=f"(p) : "l"(g_partial + i));
            s += p;
        }
#pragma unroll
        for (int off = 16; off > 0; off >>= 1)
            s += __shfl_down_sync(0xffffffffu, s, off);
        if (lane == 0) out[0] = s * (1.0f / 16384.0f);
    }
}

extern "C" void kernel_launch(void* const* d_in, const int* in_sizes, int n_in,
                              void* d_out, int out_size)
{
    const float* em     = (const float*)d_in[0];
    const float* trans  = (const float*)d_in[1];
    const float* startT = (const float*)d_in[2];
    const float* endT   = (const float*)d_in[3];
    const int*   tags   = (const int*)  d_in[4];
    // d_in[5] = mask (all ones) -> ignored
    float* out = (float*)d_out;

    crf_nll_kernel<<<GRID, TPB>>>(em, trans, startT, endT, tags, out);
}